// round 2
// baseline (speedup 1.0000x reference)
#include <cuda_runtime.h>
#include <cuda_bf16.h>
#include <math.h>

// ---------------------------------------------------------------------------
// GAT: 3 layers (H=4,C=64) -> (H=4,C=64) -> (H=1,C=64) -> FC 64->10
// N=50000 nodes, E=800000 edges (+N self loops)
// ---------------------------------------------------------------------------

#define MAX_N 50000
#define MAX_E 800000
#define MAX_ETOT (MAX_E + MAX_N)
#define NEG_SLOPE 0.2f

// Scratch (static __device__ globals; allocation-free)
__device__ float g_bufA[MAX_N * 256];
__device__ float g_bufB[MAX_N * 256];
__device__ float g_s[MAX_N * 4];
__device__ float g_d[MAX_N * 4];
__device__ float g_emax[MAX_N * 4];
__device__ float g_denom[MAX_N * 4];
__device__ float g_ebuf[MAX_ETOT * 4];

// ---------------------------------------------------------------------------
// SGEMM: C[M,N] = A[M,K] @ B[K,N], all row-major fp32.
// BM=128, BN=64, BK=16, 256 threads, 8x4 per-thread tile.
// K % 16 == 0, N % 64 == 0 (true here: K in {128,256}, N in {256,64}).
// ---------------------------------------------------------------------------
#define BM 128
#define BN 64
#define BK 16
#define TM 8
#define TN 4

__global__ __launch_bounds__(256) void sgemm_kernel(
    const float* __restrict__ A, const float* __restrict__ B,
    float* __restrict__ C, int M, int N, int K)
{
    __shared__ float As[BK][BM + 4];
    __shared__ float Bs[BK][BN];

    int tid = threadIdx.x;
    int rowBase = blockIdx.y * BM;
    int colBase = blockIdx.x * BN;

    // A tile loads: 128x16 floats = 512 float4; 2 per thread
    int aRow0 = tid >> 2;            // 0..63
    int aCol4 = (tid & 3) * 4;       // 0,4,8,12
    // B tile loads: 16x64 floats = 256 float4; 1 per thread
    int bRow  = tid >> 4;            // 0..15
    int bCol4 = (tid & 15) * 4;      // 0..60

    int ty = tid / (BN / TN);        // 0..15
    int tx = tid % (BN / TN);        // 0..15

    float acc[TM][TN];
#pragma unroll
    for (int i = 0; i < TM; i++)
#pragma unroll
        for (int j = 0; j < TN; j++) acc[i][j] = 0.f;

    for (int k0 = 0; k0 < K; k0 += BK) {
#pragma unroll
        for (int r = 0; r < 2; r++) {
            int m = aRow0 + r * 64;
            int row = rowBase + m;
            float4 v = make_float4(0.f, 0.f, 0.f, 0.f);
            if (row < M) v = *(const float4*)&A[(size_t)row * K + k0 + aCol4];
            As[aCol4 + 0][m] = v.x;
            As[aCol4 + 1][m] = v.y;
            As[aCol4 + 2][m] = v.z;
            As[aCol4 + 3][m] = v.w;
        }
        {
            float4 v = *(const float4*)&B[(size_t)(k0 + bRow) * N + colBase + bCol4];
            *(float4*)&Bs[bRow][bCol4] = v;
        }
        __syncthreads();

#pragma unroll
        for (int k = 0; k < BK; k++) {
            float ra[TM], rb[TN];
#pragma unroll
            for (int i = 0; i < TM; i++) ra[i] = As[k][ty * TM + i];
#pragma unroll
            for (int j = 0; j < TN; j++) rb[j] = Bs[k][tx * TN + j];
#pragma unroll
            for (int i = 0; i < TM; i++)
#pragma unroll
                for (int j = 0; j < TN; j++) acc[i][j] += ra[i] * rb[j];
        }
        __syncthreads();
    }

#pragma unroll
    for (int i = 0; i < TM; i++) {
        int row = rowBase + ty * TM + i;
        if (row < M) {
            float4 v = make_float4(acc[i][0], acc[i][1], acc[i][2], acc[i][3]);
            *(float4*)&C[(size_t)row * N + colBase + tx * TN] = v;
        }
    }
}

// ---------------------------------------------------------------------------
// Per-node attention coefficients: s[n,h] = <xp[n,h,:], a_src[h,:]>, same for d.
// One warp per node, loop over heads.
// ---------------------------------------------------------------------------
template <int H>
__global__ void attn_sd_kernel(const float* __restrict__ xp,
                               const float* __restrict__ a_src,
                               const float* __restrict__ a_dst,
                               float* __restrict__ s, float* __restrict__ d, int N)
{
    int warp = (blockIdx.x * blockDim.x + threadIdx.x) >> 5;
    int lane = threadIdx.x & 31;
    if (warp >= N) return;
    const int F = H * 64;
    const float* row = xp + (size_t)warp * F;
#pragma unroll
    for (int h = 0; h < H; h++) {
        float x0 = row[h * 64 + lane];
        float x1 = row[h * 64 + 32 + lane];
        float ss = x0 * __ldg(&a_src[h * 64 + lane]) + x1 * __ldg(&a_src[h * 64 + 32 + lane]);
        float dd = x0 * __ldg(&a_dst[h * 64 + lane]) + x1 * __ldg(&a_dst[h * 64 + 32 + lane]);
#pragma unroll
        for (int o = 16; o > 0; o >>= 1) {
            ss += __shfl_xor_sync(0xffffffffu, ss, o);
            dd += __shfl_xor_sync(0xffffffffu, dd, o);
        }
        if (lane == 0) {
            s[warp * H + h] = ss;
            d[warp * H + h] = dd;
        }
    }
}

// ---------------------------------------------------------------------------
// Per-layer init: agg=0, emax=-inf, denom=0
// ---------------------------------------------------------------------------
__global__ void init_layer_kernel(float* __restrict__ agg, int nAgg,
                                  float* __restrict__ emax, float* __restrict__ denom, int nH)
{
    int tid = blockIdx.x * blockDim.x + threadIdx.x;
    if (tid < nAgg) agg[tid] = 0.f;
    if (tid < nH) {
        emax[tid] = __int_as_float(0xFF800000);  // -inf
        denom[tid] = 0.f;
    }
}

__device__ __forceinline__ void atomicMaxFloat(float* addr, float val)
{
    if (val >= 0.f)
        atomicMax((int*)addr, __float_as_int(val));
    else
        atomicMin((unsigned int*)addr, __float_as_uint(val));
}

// ---------------------------------------------------------------------------
// Edge pass 1: e = leaky_relu(s[src]+d[dst]); store e; segment-max into emax[dst]
// Self loops: edge id >= E -> (i,i)
// ---------------------------------------------------------------------------
template <int H>
__global__ void edge_max_kernel(const int* __restrict__ ei, int E, int Etot,
                                const float* __restrict__ s, const float* __restrict__ d,
                                float* __restrict__ ebuf, float* __restrict__ emax)
{
    int tid = blockIdx.x * blockDim.x + threadIdx.x;
    if (tid >= Etot * H) return;
    int e = tid / H, h = tid - e * H;
    int src, dst;
    if (e < E) { src = __ldg(&ei[e]); dst = __ldg(&ei[E + e]); }
    else       { src = dst = e - E; }
    float v = s[src * H + h] + d[dst * H + h];
    v = v > 0.f ? v : NEG_SLOPE * v;
    ebuf[tid] = v;
    atomicMaxFloat(&emax[dst * H + h], v);
}

// ---------------------------------------------------------------------------
// Edge pass 2: ee = exp(e - emax[dst]); store ee; segment-sum into denom[dst]
// ---------------------------------------------------------------------------
template <int H>
__global__ void edge_exp_kernel(const int* __restrict__ ei, int E, int Etot,
                                float* __restrict__ ebuf,
                                const float* __restrict__ emax, float* __restrict__ denom)
{
    int tid = blockIdx.x * blockDim.x + threadIdx.x;
    if (tid >= Etot * H) return;
    int e = tid / H, h = tid - e * H;
    int dst;
    if (e < E) dst = __ldg(&ei[E + e]);
    else       dst = e - E;
    float ee = expf(ebuf[tid] - emax[dst * H + h]);
    ebuf[tid] = ee;
    atomicAdd(&denom[dst * H + h], ee);
}

// ---------------------------------------------------------------------------
// Vectorized fp32 reduction to global (sm_90+): 4x fewer L2 atomic slots
// ---------------------------------------------------------------------------
__device__ __forceinline__ void redAdd4(float* addr, float4 v)
{
    asm volatile("red.global.add.v4.f32 [%0], {%1, %2, %3, %4};"
                 :: "l"(addr), "f"(v.x), "f"(v.y), "f"(v.z), "f"(v.w)
                 : "memory");
}

// ---------------------------------------------------------------------------
// Edge pass 3: agg[dst] += alpha * xp[src].  One warp per edge; float4 lanes.
// ---------------------------------------------------------------------------
template <int H>
__global__ void agg_kernel(const int* __restrict__ ei, int E, int Etot,
                           const float* __restrict__ ebuf, const float* __restrict__ denom,
                           const float* __restrict__ xp, float* __restrict__ agg)
{
    int warp = (blockIdx.x * blockDim.x + threadIdx.x) >> 5;
    int lane = threadIdx.x & 31;
    if (warp >= Etot) return;
    int e = warp;
    int src, dst;
    if (e < E) { src = __ldg(&ei[e]); dst = __ldg(&ei[E + e]); }
    else       { src = dst = e - E; }

    float myAlpha = 0.f;
    if (lane < H)
        myAlpha = ebuf[e * H + lane] / (denom[dst * H + lane] + 1e-16f);

    const int F = H * 64;
    const float* xrow = xp + (size_t)src * F;
    float* arow = agg + (size_t)dst * F;

#pragma unroll
    for (int base = 0; base < F; base += 128) {
        int pos = base + lane * 4;
        int h = (pos >> 6) & 31;  // in-range for shfl even for inactive lanes
        float al = __shfl_sync(0xffffffffu, myAlpha, h);
        if (pos < F) {
            float4 xv = *(const float4*)&xrow[pos];
            redAdd4(&arow[pos], make_float4(al * xv.x, al * xv.y, al * xv.z, al * xv.w));
        }
    }
}

// ---------------------------------------------------------------------------
// out = relu(agg + b)
// ---------------------------------------------------------------------------
__global__ void bias_relu_kernel(float* __restrict__ a, const float* __restrict__ b,
                                 int total, int F)
{
    int tid = blockIdx.x * blockDim.x + threadIdx.x;
    if (tid >= total) return;
    float v = a[tid] + __ldg(&b[tid % F]);
    a[tid] = v > 0.f ? v : 0.f;
}

// ---------------------------------------------------------------------------
// Final FC: out[n,10] = h[n,64] @ Wfc + bfc
// ---------------------------------------------------------------------------
__global__ void fc_kernel(const float* __restrict__ h, const float* __restrict__ W,
                          const float* __restrict__ b, float* __restrict__ out, int N)
{
    int tid = blockIdx.x * blockDim.x + threadIdx.x;
    if (tid >= N * 10) return;
    int n = tid / 10, j = tid - n * 10;
    const float* row = h + (size_t)n * 64;
    float acc = __ldg(&b[j]);
#pragma unroll
    for (int k = 0; k < 64; k++)
        acc += row[k] * __ldg(&W[k * 10 + j]);
    out[tid] = acc;
}

// ---------------------------------------------------------------------------
// Orchestration
// ---------------------------------------------------------------------------
static inline int ceil_div(int a, int b) { return (a + b - 1) / b; }

template <int H>
static void run_gat_layer(const float* act_in, int K, const int* ei, int E, int Etot, int N,
                          const float* W, const float* a_src, const float* a_dst, const float* b,
                          float* xp /*bufA*/, float* agg /*bufB*/,
                          float* s, float* d, float* emax, float* denom, float* ebuf)
{
    const int F = H * 64;
    // 1) xp = act_in @ W
    sgemm_kernel<<<dim3(F / BN, ceil_div(N, BM)), 256>>>(act_in, W, xp, N, F, K);
    // 2) s, d
    attn_sd_kernel<H><<<ceil_div(N * 32, 256), 256>>>(xp, a_src, a_dst, s, d, N);
    // 3) init agg/emax/denom
    init_layer_kernel<<<ceil_div(N * F, 256), 256>>>(agg, N * F, emax, denom, N * H);
    // 4) e + segment max
    edge_max_kernel<H><<<ceil_div(Etot * H, 256), 256>>>(ei, E, Etot, s, d, ebuf, emax);
    // 5) exp + segment sum
    edge_exp_kernel<H><<<ceil_div(Etot * H, 256), 256>>>(ei, E, Etot, ebuf, emax, denom);
    // 6) aggregate
    agg_kernel<H><<<ceil_div(Etot * 32, 256), 256>>>(ei, E, Etot, ebuf, denom, xp, agg);
    // 7) bias + relu
    bias_relu_kernel<<<ceil_div(N * F, 256), 256>>>(agg, b, N * F, F);
}

extern "C" void kernel_launch(void* const* d_in, const int* in_sizes, int n_in,
                              void* d_out, int out_size)
{
    const float* x    = (const float*)d_in[0];
    const int*   ei   = (const int*)d_in[1];
    const float* W1   = (const float*)d_in[2];
    const float* as1  = (const float*)d_in[3];
    const float* ad1  = (const float*)d_in[4];
    const float* b1   = (const float*)d_in[5];
    const float* W2   = (const float*)d_in[6];
    const float* as2  = (const float*)d_in[7];
    const float* ad2  = (const float*)d_in[8];
    const float* b2   = (const float*)d_in[9];
    const float* W3   = (const float*)d_in[10];
    const float* as3  = (const float*)d_in[11];
    const float* ad3  = (const float*)d_in[12];
    const float* b3   = (const float*)d_in[13];
    const float* Wfc  = (const float*)d_in[14];
    const float* bfc  = (const float*)d_in[15];
    float* out = (float*)d_out;

    int N = in_sizes[0] / 128;
    int E = in_sizes[1] / 2;
    int Etot = E + N;

    float *bufA, *bufB, *s, *d, *emax, *denom, *ebuf;
    cudaGetSymbolAddress((void**)&bufA, g_bufA);
    cudaGetSymbolAddress((void**)&bufB, g_bufB);
    cudaGetSymbolAddress((void**)&s, g_s);
    cudaGetSymbolAddress((void**)&d, g_d);
    cudaGetSymbolAddress((void**)&emax, g_emax);
    cudaGetSymbolAddress((void**)&denom, g_denom);
    cudaGetSymbolAddress((void**)&ebuf, g_ebuf);

    // Layer 1: 128 -> 256 (H=4, C=64)
    run_gat_layer<4>(x, 128, ei, E, Etot, N, W1, as1, ad1, b1,
                     bufA, bufB, s, d, emax, denom, ebuf);
    // Layer 2: 256 -> 256 (H=4)
    run_gat_layer<4>(bufB, 256, ei, E, Etot, N, W2, as2, ad2, b2,
                     bufA, bufB, s, d, emax, denom, ebuf);
    // Layer 3: 256 -> 64 (H=1)
    run_gat_layer<1>(bufB, 256, ei, E, Etot, N, W3, as3, ad3, b3,
                     bufA, bufB, s, d, emax, denom, ebuf);
    // FC: 64 -> 10
    fc_kernel<<<ceil_div(N * 10, 256), 256>>>(bufB, Wfc, bfc, out, N);
}

// round 3
// speedup vs baseline: 1.5282x; 1.5282x over previous
#include <cuda_runtime.h>
#include <cuda_bf16.h>
#include <math.h>

// ---------------------------------------------------------------------------
// GAT: 3 layers (H=4,C=64) -> (H=4,C=64) -> (H=1,C=64) -> FC 64->10
// N=50000 nodes, E=800000 edges (+N self loops)
// Strategy: per-call CSR build (by dst), then one fused warp-per-node kernel
// per layer (online softmax + gather aggregation, no atomics in hot path),
// plus a 128x128 double-buffered SGEMM.
// ---------------------------------------------------------------------------

#define MAX_N 50000
#define MAX_E 800000
#define MAX_ETOT (MAX_E + MAX_N)
#define NEG_SLOPE 0.2f
#define SCAN_BS 512

// Scratch (static __device__ globals; allocation-free)
__device__ float g_bufA[MAX_N * 256];
__device__ float g_bufB[MAX_N * 256];
__device__ float g_s[MAX_N * 4];
__device__ float g_d[MAX_N * 4];
__device__ int   g_count[MAX_N];
__device__ int   g_excl[MAX_N];
__device__ int   g_cursor[MAX_N];
__device__ int   g_ptr[MAX_N + 1];
__device__ int   g_bsum[256];
__device__ int   g_csr[MAX_ETOT];

static inline int ceil_div(int a, int b) { return (a + b - 1) / b; }

// ---------------------------------------------------------------------------
// CSR build
// ---------------------------------------------------------------------------
__global__ void zero_count_kernel(int* __restrict__ count, int N)
{
    int i = blockIdx.x * blockDim.x + threadIdx.x;
    if (i < N) count[i] = 0;
}

__global__ void count_kernel(const int* __restrict__ ei, int E, int Etot,
                             int* __restrict__ count)
{
    int e = blockIdx.x * blockDim.x + threadIdx.x;
    if (e >= Etot) return;
    int dst = (e < E) ? __ldg(&ei[E + e]) : (e - E);
    atomicAdd(&count[dst], 1);
}

__global__ void scan_block_kernel(const int* __restrict__ count, int* __restrict__ excl,
                                  int* __restrict__ bsum, int N)
{
    __shared__ int sh[SCAN_BS];
    int t = threadIdx.x;
    int idx = blockIdx.x * SCAN_BS + t;
    int v = (idx < N) ? count[idx] : 0;
    sh[t] = v;
    __syncthreads();
#pragma unroll
    for (int o = 1; o < SCAN_BS; o <<= 1) {
        int add = (t >= o) ? sh[t - o] : 0;
        __syncthreads();
        sh[t] += add;
        __syncthreads();
    }
    if (idx < N) excl[idx] = sh[t] - v;
    if (t == SCAN_BS - 1) bsum[blockIdx.x] = sh[t];
}

__global__ void scan_sums_kernel(int* __restrict__ bsum, int nb)
{
    __shared__ int sh[256];
    int t = threadIdx.x;
    int v = (t < nb) ? bsum[t] : 0;
    sh[t] = v;
    __syncthreads();
#pragma unroll
    for (int o = 1; o < 256; o <<= 1) {
        int add = (t >= o) ? sh[t - o] : 0;
        __syncthreads();
        sh[t] += add;
        __syncthreads();
    }
    if (t < nb) bsum[t] = sh[t] - v;  // exclusive
}

__global__ void scan_finish_kernel(const int* __restrict__ excl, const int* __restrict__ bsum,
                                   int* __restrict__ ptr, int* __restrict__ cursor,
                                   int N, int Etot)
{
    int i = blockIdx.x * blockDim.x + threadIdx.x;
    if (i < N) {
        int p = excl[i] + bsum[i / SCAN_BS];
        ptr[i] = p;
        cursor[i] = p;
    }
    if (i == 0) ptr[N] = Etot;
}

__global__ void scatter_kernel(const int* __restrict__ ei, int E, int Etot,
                               int* __restrict__ cursor, int* __restrict__ csr)
{
    int e = blockIdx.x * blockDim.x + threadIdx.x;
    if (e >= Etot) return;
    int src, dst;
    if (e < E) { src = __ldg(&ei[e]); dst = __ldg(&ei[E + e]); }
    else       { src = dst = e - E; }
    int pos = atomicAdd(&cursor[dst], 1);
    csr[pos] = src;
}

// ---------------------------------------------------------------------------
// SGEMM: C[M,N] = A[M,K] @ B[K,N], row-major fp32.
// BM=128, BK=16, 256 threads, double-buffered smem, per-thread TMxTN tile.
// Requires N % BN_ == 0 and K % 16 == 0.
// ---------------------------------------------------------------------------
template <int BN_, int TN_>
__global__ __launch_bounds__(256) void sgemm_kernel(
    const float* __restrict__ A, const float* __restrict__ B,
    float* __restrict__ C, int M, int N, int K)
{
    constexpr int BM_ = 128, BK_ = 16, TM_ = 8;
    constexpr int AV = (BM_ * BK_) / (256 * 4);  // float4 A loads per thread (2)
    constexpr int BV = (BK_ * BN_) / (256 * 4);  // float4 B loads per thread (2 or 1)

    __shared__ float As[2][BK_][BM_ + 4];
    __shared__ float Bs[2][BK_][BN_];

    int tid = threadIdx.x;
    int rowBase = blockIdx.y * BM_;
    int colBase = blockIdx.x * BN_;
    int ty = tid >> 4;   // 0..15
    int tx = tid & 15;   // 0..15

    float4 aReg[AV];
    float4 bReg[BV];

    auto loadA = [&](int k0) {
#pragma unroll
        for (int l = 0; l < AV; l++) {
            int li = tid + l * 256;
            int r = li >> 2;
            int c = (li & 3) * 4;
            int row = rowBase + r;
            aReg[l] = (row < M) ? *(const float4*)&A[(size_t)row * K + k0 + c]
                                : make_float4(0.f, 0.f, 0.f, 0.f);
        }
    };
    auto loadB = [&](int k0) {
#pragma unroll
        for (int l = 0; l < BV; l++) {
            int li = tid + l * 256;
            int r = li / (BN_ / 4);
            int c = (li % (BN_ / 4)) * 4;
            bReg[l] = *(const float4*)&B[(size_t)(k0 + r) * N + colBase + c];
        }
    };
    auto storeTiles = [&](int buf) {
#pragma unroll
        for (int l = 0; l < AV; l++) {
            int li = tid + l * 256;
            int r = li >> 2;
            int c = (li & 3) * 4;
            As[buf][c + 0][r] = aReg[l].x;
            As[buf][c + 1][r] = aReg[l].y;
            As[buf][c + 2][r] = aReg[l].z;
            As[buf][c + 3][r] = aReg[l].w;
        }
#pragma unroll
        for (int l = 0; l < BV; l++) {
            int li = tid + l * 256;
            int r = li / (BN_ / 4);
            int c = (li % (BN_ / 4)) * 4;
            *(float4*)&Bs[buf][r][c] = bReg[l];
        }
    };

    float acc[TM_][TN_];
#pragma unroll
    for (int i = 0; i < TM_; i++)
#pragma unroll
        for (int j = 0; j < TN_; j++) acc[i][j] = 0.f;

    int tiles = K / BK_;
    loadA(0); loadB(0);
    storeTiles(0);
    __syncthreads();

    for (int t = 0; t < tiles; t++) {
        int cur = t & 1;
        if (t + 1 < tiles) { loadA((t + 1) * BK_); loadB((t + 1) * BK_); }
#pragma unroll
        for (int k = 0; k < BK_; k++) {
            float ra[TM_], rb[TN_];
#pragma unroll
            for (int v = 0; v < TM_ / 4; v++)
                *(float4*)&ra[v * 4] = *(const float4*)&As[cur][k][ty * TM_ + v * 4];
#pragma unroll
            for (int v = 0; v < TN_ / 4; v++)
                *(float4*)&rb[v * 4] = *(const float4*)&Bs[cur][k][tx * TN_ + v * 4];
#pragma unroll
            for (int i = 0; i < TM_; i++)
#pragma unroll
                for (int j = 0; j < TN_; j++) acc[i][j] += ra[i] * rb[j];
        }
        if (t + 1 < tiles) {
            __syncthreads();
            storeTiles(cur ^ 1);
            __syncthreads();
        }
    }

#pragma unroll
    for (int i = 0; i < TM_; i++) {
        int row = rowBase + ty * TM_ + i;
        if (row < M) {
#pragma unroll
            for (int v = 0; v < TN_ / 4; v++) {
                float4 o = make_float4(acc[i][v * 4 + 0], acc[i][v * 4 + 1],
                                       acc[i][v * 4 + 2], acc[i][v * 4 + 3]);
                *(float4*)&C[(size_t)row * N + colBase + tx * TN_ + v * 4] = o;
            }
        }
    }
}

// ---------------------------------------------------------------------------
// Per-node attention coefficients: s[n,h] = <xp[n,h,:], a_src[h,:]>, same for d.
// ---------------------------------------------------------------------------
template <int H>
__global__ void attn_sd_kernel(const float* __restrict__ xp,
                               const float* __restrict__ a_src,
                               const float* __restrict__ a_dst,
                               float* __restrict__ s, float* __restrict__ d, int N)
{
    int warp = (blockIdx.x * blockDim.x + threadIdx.x) >> 5;
    int lane = threadIdx.x & 31;
    if (warp >= N) return;
    const int F = H * 64;
    const float* row = xp + (size_t)warp * F;
#pragma unroll
    for (int h = 0; h < H; h++) {
        float x0 = row[h * 64 + lane];
        float x1 = row[h * 64 + 32 + lane];
        float ss = x0 * __ldg(&a_src[h * 64 + lane]) + x1 * __ldg(&a_src[h * 64 + 32 + lane]);
        float dd = x0 * __ldg(&a_dst[h * 64 + lane]) + x1 * __ldg(&a_dst[h * 64 + 32 + lane]);
#pragma unroll
        for (int o = 16; o > 0; o >>= 1) {
            ss += __shfl_xor_sync(0xffffffffu, ss, o);
            dd += __shfl_xor_sync(0xffffffffu, dd, o);
        }
        if (lane == 0) {
            s[warp * H + h] = ss;
            d[warp * H + h] = dd;
        }
    }
}

// ---------------------------------------------------------------------------
// Fused GAT per-node kernel: one warp per destination node.
// Pass 1: online softmax (max + scaled sum) over incoming edges.
// Pass 2: gather-aggregate alpha * xp[src], then bias + ReLU, single write.
// ---------------------------------------------------------------------------
template <int H>
__global__ __launch_bounds__(256) void gat_fused_kernel(
    const int* __restrict__ ptr, const int* __restrict__ csr,
    const float* __restrict__ s, const float* __restrict__ dco,
    const float* __restrict__ xp, const float* __restrict__ bias,
    float* __restrict__ out, int N)
{
    constexpr int F = H * 64;
    constexpr int PL = F / 32;  // floats per lane (8 for H=4, 2 for H=1)

    int warp = (blockIdx.x * blockDim.x + threadIdx.x) >> 5;
    int lane = threadIdx.x & 31;
    if (warp >= N) return;
    int n = warp;
    int beg = __ldg(&ptr[n]);
    int end = __ldg(&ptr[n + 1]);

    // destination coefficients
    float dh[H];
#pragma unroll
    for (int h = 0; h < H; h++) dh[h] = __ldg(&dco[n * H + h]);

    // Pass 1: online max + sum per head
    float m[H], ssum[H];
#pragma unroll
    for (int h = 0; h < H; h++) { m[h] = -1e30f; ssum[h] = 0.f; }

    for (int i = beg + lane; i < end; i += 32) {
        int src = __ldg(&csr[i]);
        float sv[H];
        if (H == 4) {
            float4 t4 = __ldg((const float4*)s + src);
            sv[0] = t4.x; sv[1] = t4.y; sv[2] = t4.z; sv[3] = t4.w;
        } else {
            sv[0] = __ldg(&s[src]);
        }
#pragma unroll
        for (int h = 0; h < H; h++) {
            float e = sv[h] + dh[h];
            e = e > 0.f ? e : NEG_SLOPE * e;
            float nm = fmaxf(m[h], e);
            ssum[h] = ssum[h] * __expf(m[h] - nm) + __expf(e - nm);
            m[h] = nm;
        }
    }
    // warp combine (butterfly: all lanes end with final result)
#pragma unroll
    for (int o = 16; o > 0; o >>= 1) {
#pragma unroll
        for (int h = 0; h < H; h++) {
            float om = __shfl_xor_sync(0xffffffffu, m[h], o);
            float os = __shfl_xor_sync(0xffffffffu, ssum[h], o);
            float nm = fmaxf(m[h], om);
            ssum[h] = ssum[h] * __expf(m[h] - nm) + os * __expf(om - nm);
            m[h] = nm;
        }
    }

    // Pass 2: aggregate
    const int myh = (lane * PL) >> 6;
    const float mh = m[myh];
    const float iv = 1.f / (ssum[myh] + 1e-16f);
    const float dmy = dh[myh];

    float acc[PL];
#pragma unroll
    for (int j = 0; j < PL; j++) acc[j] = 0.f;

    for (int i = beg; i < end; i++) {
        int src = __ldg(&csr[i]);  // uniform within warp -> broadcast
        float e = __ldg(&s[src * H + myh]) + dmy;
        e = e > 0.f ? e : NEG_SLOPE * e;
        float alpha = __expf(e - mh) * iv;
        if (PL == 8) {
            const float4* xr = (const float4*)(xp + (size_t)src * F);
            float4 v0 = __ldg(xr + lane * 2);
            float4 v1 = __ldg(xr + lane * 2 + 1);
            acc[0] += alpha * v0.x; acc[1] += alpha * v0.y;
            acc[2] += alpha * v0.z; acc[3] += alpha * v0.w;
            acc[4] += alpha * v1.x; acc[5] += alpha * v1.y;
            acc[6] += alpha * v1.z; acc[7] += alpha * v1.w;
        } else {
            float2 v = __ldg((const float2*)(xp + (size_t)src * F) + lane);
            acc[0] += alpha * v.x;
            acc[1] += alpha * v.y;
        }
    }

    // bias + relu + store
#pragma unroll
    for (int j = 0; j < PL; j++) {
        float v = acc[j] + __ldg(&bias[lane * PL + j]);
        acc[j] = v > 0.f ? v : 0.f;
    }
    if (PL == 8) {
        float4* orow = (float4*)(out + (size_t)n * F);
        orow[lane * 2]     = make_float4(acc[0], acc[1], acc[2], acc[3]);
        orow[lane * 2 + 1] = make_float4(acc[4], acc[5], acc[6], acc[7]);
    } else {
        ((float2*)(out + (size_t)n * F))[lane] = make_float2(acc[0], acc[1]);
    }
}

// ---------------------------------------------------------------------------
// Final FC: out[n,10] = h[n,64] @ Wfc + bfc
// ---------------------------------------------------------------------------
__global__ void fc_kernel(const float* __restrict__ h, const float* __restrict__ W,
                          const float* __restrict__ b, float* __restrict__ out, int N)
{
    int tid = blockIdx.x * blockDim.x + threadIdx.x;
    if (tid >= N * 10) return;
    int n = tid / 10, j = tid - n * 10;
    const float* row = h + (size_t)n * 64;
    float acc = __ldg(&b[j]);
#pragma unroll
    for (int k = 0; k < 64; k++)
        acc += row[k] * __ldg(&W[k * 10 + j]);
    out[tid] = acc;
}

// ---------------------------------------------------------------------------
// Orchestration
// ---------------------------------------------------------------------------
template <int H>
static void run_gat_layer(const float* act_in, int K, int N,
                          const float* W, const float* a_src, const float* a_dst,
                          const float* b, const int* ptr, const int* csr,
                          float* xp, float* s, float* d, float* out)
{
    const int F = H * 64;
    if (F == 256)
        sgemm_kernel<128, 8><<<dim3(F / 128, ceil_div(N, 128)), 256>>>(act_in, W, xp, N, F, K);
    else
        sgemm_kernel<64, 4><<<dim3(F / 64, ceil_div(N, 128)), 256>>>(act_in, W, xp, N, F, K);
    attn_sd_kernel<H><<<ceil_div(N * 32, 256), 256>>>(xp, a_src, a_dst, s, d, N);
    gat_fused_kernel<H><<<ceil_div(N * 32, 256), 256>>>(ptr, csr, s, d, xp, b, out, N);
}

extern "C" void kernel_launch(void* const* d_in, const int* in_sizes, int n_in,
                              void* d_out, int out_size)
{
    const float* x    = (const float*)d_in[0];
    const int*   ei   = (const int*)d_in[1];
    const float* W1   = (const float*)d_in[2];
    const float* as1  = (const float*)d_in[3];
    const float* ad1  = (const float*)d_in[4];
    const float* b1   = (const float*)d_in[5];
    const float* W2   = (const float*)d_in[6];
    const float* as2  = (const float*)d_in[7];
    const float* ad2  = (const float*)d_in[8];
    const float* b2   = (const float*)d_in[9];
    const float* W3   = (const float*)d_in[10];
    const float* as3  = (const float*)d_in[11];
    const float* ad3  = (const float*)d_in[12];
    const float* b3   = (const float*)d_in[13];
    const float* Wfc  = (const float*)d_in[14];
    const float* bfc  = (const float*)d_in[15];
    float* out = (float*)d_out;

    int N = in_sizes[0] / 128;
    int E = in_sizes[1] / 2;
    int Etot = E + N;

    float *bufA, *bufB, *s, *d;
    int *count, *excl, *cursor, *ptr, *bsum, *csr;
    cudaGetSymbolAddress((void**)&bufA, g_bufA);
    cudaGetSymbolAddress((void**)&bufB, g_bufB);
    cudaGetSymbolAddress((void**)&s, g_s);
    cudaGetSymbolAddress((void**)&d, g_d);
    cudaGetSymbolAddress((void**)&count, g_count);
    cudaGetSymbolAddress((void**)&excl, g_excl);
    cudaGetSymbolAddress((void**)&cursor, g_cursor);
    cudaGetSymbolAddress((void**)&ptr, g_ptr);
    cudaGetSymbolAddress((void**)&bsum, g_bsum);
    cudaGetSymbolAddress((void**)&csr, g_csr);

    // --- CSR build (by destination) ---
    int nb = ceil_div(N, SCAN_BS);
    zero_count_kernel<<<ceil_div(N, 256), 256>>>(count, N);
    count_kernel<<<ceil_div(Etot, 256), 256>>>(ei, E, Etot, count);
    scan_block_kernel<<<nb, SCAN_BS>>>(count, excl, bsum, N);
    scan_sums_kernel<<<1, 256>>>(bsum, nb);
    scan_finish_kernel<<<ceil_div(N, 256), 256>>>(excl, bsum, ptr, cursor, N, Etot);
    scatter_kernel<<<ceil_div(Etot, 256), 256>>>(ei, E, Etot, cursor, csr);

    // --- Layers ---
    run_gat_layer<4>(x,    128, N, W1, as1, ad1, b1, ptr, csr, bufA, s, d, bufB);
    run_gat_layer<4>(bufB, 256, N, W2, as2, ad2, b2, ptr, csr, bufA, s, d, bufB);
    run_gat_layer<1>(bufB, 256, N, W3, as3, ad3, b3, ptr, csr, bufA, s, d, bufB);

    // --- FC ---
    fc_kernel<<<ceil_div(N * 10, 256), 256>>>(bufB, Wfc, bfc, out, N);
}

// round 4
// speedup vs baseline: 2.5000x; 1.6359x over previous
#include <cuda_runtime.h>
#include <cuda_bf16.h>
#include <math.h>
#include <stdint.h>

// ---------------------------------------------------------------------------
// GAT: 3 layers (H=4,C=64) -> (H=4,C=64) -> (H=1,C=64) -> FC 64->10
// N=50000 nodes, E=800000 edges (+N self loops)
// R3: TF32 tensor-core GEMM (mma.m16n8k8) with fused s/d epilogue.
// ---------------------------------------------------------------------------

#define MAX_N 50000
#define MAX_E 800000
#define MAX_ETOT (MAX_E + MAX_N)
#define NEG_SLOPE 0.2f
#define SCAN_BS 512

// Scratch (static __device__ globals; allocation-free)
__device__ float g_bufA[MAX_N * 256];
__device__ float g_bufB[MAX_N * 256];
__device__ float g_s[MAX_N * 4];
__device__ float g_d[MAX_N * 4];
__device__ int   g_count[MAX_N];
__device__ int   g_excl[MAX_N];
__device__ int   g_cursor[MAX_N];
__device__ int   g_ptr[MAX_N + 1];
__device__ int   g_bsum[256];
__device__ int   g_csr[MAX_ETOT];

static inline int ceil_div(int a, int b) { return (a + b - 1) / b; }

// ---------------------------------------------------------------------------
// CSR build
// ---------------------------------------------------------------------------
__global__ void zero_count_kernel(int* __restrict__ count, int N)
{
    int i = blockIdx.x * blockDim.x + threadIdx.x;
    if (i < N) count[i] = 0;
}

__global__ void count_kernel(const int* __restrict__ ei, int E, int Etot,
                             int* __restrict__ count)
{
    int e = blockIdx.x * blockDim.x + threadIdx.x;
    if (e >= Etot) return;
    int dst = (e < E) ? __ldg(&ei[E + e]) : (e - E);
    atomicAdd(&count[dst], 1);
}

__global__ void scan_block_kernel(const int* __restrict__ count, int* __restrict__ excl,
                                  int* __restrict__ bsum, int N)
{
    __shared__ int sh[SCAN_BS];
    int t = threadIdx.x;
    int idx = blockIdx.x * SCAN_BS + t;
    int v = (idx < N) ? count[idx] : 0;
    sh[t] = v;
    __syncthreads();
#pragma unroll
    for (int o = 1; o < SCAN_BS; o <<= 1) {
        int add = (t >= o) ? sh[t - o] : 0;
        __syncthreads();
        sh[t] += add;
        __syncthreads();
    }
    if (idx < N) excl[idx] = sh[t] - v;
    if (t == SCAN_BS - 1) bsum[blockIdx.x] = sh[t];
}

__global__ void scan_sums_kernel(int* __restrict__ bsum, int nb)
{
    __shared__ int sh[256];
    int t = threadIdx.x;
    int v = (t < nb) ? bsum[t] : 0;
    sh[t] = v;
    __syncthreads();
#pragma unroll
    for (int o = 1; o < 256; o <<= 1) {
        int add = (t >= o) ? sh[t - o] : 0;
        __syncthreads();
        sh[t] += add;
        __syncthreads();
    }
    if (t < nb) bsum[t] = sh[t] - v;  // exclusive
}

__global__ void scan_finish_kernel(const int* __restrict__ excl, const int* __restrict__ bsum,
                                   int* __restrict__ ptr, int* __restrict__ cursor,
                                   int N, int Etot)
{
    int i = blockIdx.x * blockDim.x + threadIdx.x;
    if (i < N) {
        int p = excl[i] + bsum[i / SCAN_BS];
        ptr[i] = p;
        cursor[i] = p;
    }
    if (i == 0) ptr[N] = Etot;
}

__global__ void scatter_kernel(const int* __restrict__ ei, int E, int Etot,
                               int* __restrict__ cursor, int* __restrict__ csr)
{
    int e = blockIdx.x * blockDim.x + threadIdx.x;
    if (e >= Etot) return;
    int src, dst;
    if (e < E) { src = __ldg(&ei[e]); dst = __ldg(&ei[E + e]); }
    else       { src = dst = e - E; }
    int pos = atomicAdd(&cursor[dst], 1);
    csr[pos] = src;
}

// ---------------------------------------------------------------------------
// TF32 helpers
// ---------------------------------------------------------------------------
__device__ __forceinline__ uint32_t f2tf32(float f)
{
    uint32_t o;
    asm("cvt.rna.tf32.f32 %0, %1;" : "=r"(o) : "f"(f));
    return o;
}

__device__ __forceinline__ void mma_tf32(float* c, const uint32_t* a, const uint32_t* b)
{
    asm volatile(
        "mma.sync.aligned.m16n8k8.row.col.f32.tf32.tf32.f32 "
        "{%0,%1,%2,%3}, {%4,%5,%6,%7}, {%8,%9}, {%0,%1,%2,%3};\n"
        : "+f"(c[0]), "+f"(c[1]), "+f"(c[2]), "+f"(c[3])
        : "r"(a[0]), "r"(a[1]), "r"(a[2]), "r"(a[3]), "r"(b[0]), "r"(b[1]));
}

// ---------------------------------------------------------------------------
// TF32 tensor-core GEMM: C[M,N] = A[M,K] @ B[K,N], row-major fp32 in/out.
// BM=128, BK=32, 256 threads (8 warps), warp tile 32x64 (BN=128) / 16x64 (BN=64).
// Fused epilogue: s[n,h] = <xp_row_head, a_src_h>, d likewise (each warp owns
// one full 64-col head slice).
// Requires K % 32 == 0, N % BN_ == 0.
// ---------------------------------------------------------------------------
template <int BN_>
__global__ __launch_bounds__(256) void mma_gemm_kernel(
    const float* __restrict__ A, const float* __restrict__ B,
    float* __restrict__ C, int M, int N, int K,
    const float* __restrict__ a_src, const float* __restrict__ a_dst,
    float* __restrict__ s_out, float* __restrict__ d_out, int H)
{
    constexpr int BM_ = 128, BK_ = 32;
    constexpr int MI = (BN_ == 128) ? 2 : 1;   // 16-row mma tiles per warp
    constexpr int NI = 8;                      // 8-col mma tiles per warp
    constexpr int AV = 4;                      // float4 A loads/thread (128*32/1024)
    constexpr int BV = (BK_ * BN_) / 1024;     // float4 B loads/thread (4 or 2)

    __shared__ uint32_t As[BM_][40];           // [m][k], pad 40 -> conflict-free frag reads
    __shared__ uint32_t Bs[BK_][BN_ + 8];      // [k][n], pad 8  -> conflict-free frag reads

    const int tid = threadIdx.x;
    const int wid = tid >> 5;
    const int lane = tid & 31;
    const int g = lane >> 2;      // groupID
    const int t4 = lane & 3;      // threadID_in_group

    const int rowBase = blockIdx.y * BM_;
    const int colBase = blockIdx.x * BN_;
    const int warp_m = (BN_ == 128) ? (wid >> 1) * 32 : wid * 16;
    const int warp_n = (BN_ == 128) ? (wid & 1) * 64 : 0;

    float4 aReg[AV];
    float4 bReg[BV];

    auto loadRegs = [&](int k0) {
#pragma unroll
        for (int l = 0; l < AV; l++) {
            int li = tid + l * 256;
            int m = li >> 3;
            int k4 = (li & 7) * 4;
            int row = rowBase + m;
            aReg[l] = (row < M) ? *(const float4*)&A[(size_t)row * K + k0 + k4]
                                : make_float4(0.f, 0.f, 0.f, 0.f);
        }
#pragma unroll
        for (int l = 0; l < BV; l++) {
            int li = tid + l * 256;
            int r = li / (BN_ / 4);
            int c4 = (li % (BN_ / 4)) * 4;
            bReg[l] = *(const float4*)&B[(size_t)(k0 + r) * N + colBase + c4];
        }
    };
    auto storeSmem = [&]() {
#pragma unroll
        for (int l = 0; l < AV; l++) {
            int li = tid + l * 256;
            int m = li >> 3;
            int k4 = (li & 7) * 4;
            As[m][k4 + 0] = f2tf32(aReg[l].x);
            As[m][k4 + 1] = f2tf32(aReg[l].y);
            As[m][k4 + 2] = f2tf32(aReg[l].z);
            As[m][k4 + 3] = f2tf32(aReg[l].w);
        }
#pragma unroll
        for (int l = 0; l < BV; l++) {
            int li = tid + l * 256;
            int r = li / (BN_ / 4);
            int c4 = (li % (BN_ / 4)) * 4;
            Bs[r][c4 + 0] = f2tf32(bReg[l].x);
            Bs[r][c4 + 1] = f2tf32(bReg[l].y);
            Bs[r][c4 + 2] = f2tf32(bReg[l].z);
            Bs[r][c4 + 3] = f2tf32(bReg[l].w);
        }
    };

    float acc[MI][NI][4];
#pragma unroll
    for (int mi = 0; mi < MI; mi++)
#pragma unroll
        for (int ni = 0; ni < NI; ni++)
#pragma unroll
            for (int j = 0; j < 4; j++) acc[mi][ni][j] = 0.f;

    const int tiles = K / BK_;
    loadRegs(0);

    for (int t = 0; t < tiles; t++) {
        storeSmem();
        __syncthreads();
        if (t + 1 < tiles) loadRegs((t + 1) * BK_);

#pragma unroll
        for (int kk = 0; kk < BK_ / 8; kk++) {
            uint32_t af[MI][4], bf[NI][2];
#pragma unroll
            for (int mi = 0; mi < MI; mi++) {
                int m = warp_m + mi * 16;
                af[mi][0] = As[m + g][kk * 8 + t4];
                af[mi][1] = As[m + 8 + g][kk * 8 + t4];
                af[mi][2] = As[m + g][kk * 8 + t4 + 4];
                af[mi][3] = As[m + 8 + g][kk * 8 + t4 + 4];
            }
#pragma unroll
            for (int ni = 0; ni < NI; ni++) {
                int n = warp_n + ni * 8 + g;
                bf[ni][0] = Bs[kk * 8 + t4][n];
                bf[ni][1] = Bs[kk * 8 + t4 + 4][n];
            }
#pragma unroll
            for (int mi = 0; mi < MI; mi++)
#pragma unroll
                for (int ni = 0; ni < NI; ni++)
                    mma_tf32(acc[mi][ni], af[mi], bf[ni]);
        }
        __syncthreads();
    }

    // ---- Epilogue: store C + fused attention coefficients ----
    // Fragment C: c0 (g, 2t4), c1 (g, 2t4+1), c2 (g+8, 2t4), c3 (g+8, 2t4+1)
    const int head = (colBase + warp_n) >> 6;
    const float* ah = a_src + head * 64;
    const float* dh = a_dst + head * 64;
    float2 av[NI], dv[NI];
#pragma unroll
    for (int ni = 0; ni < NI; ni++) {
        av[ni] = *(const float2*)&ah[ni * 8 + 2 * t4];
        dv[ni] = *(const float2*)&dh[ni * 8 + 2 * t4];
    }

#pragma unroll
    for (int mi = 0; mi < MI; mi++) {
        int r0 = rowBase + warp_m + mi * 16 + g;
        int r1 = r0 + 8;
        float s0 = 0.f, s1 = 0.f, d0 = 0.f, d1 = 0.f;
#pragma unroll
        for (int ni = 0; ni < NI; ni++) {
            float c0 = acc[mi][ni][0], c1 = acc[mi][ni][1];
            float c2 = acc[mi][ni][2], c3 = acc[mi][ni][3];
            int col = colBase + warp_n + ni * 8 + 2 * t4;
            if (r0 < M) *(float2*)&C[(size_t)r0 * N + col] = make_float2(c0, c1);
            if (r1 < M) *(float2*)&C[(size_t)r1 * N + col] = make_float2(c2, c3);
            s0 += c0 * av[ni].x + c1 * av[ni].y;
            s1 += c2 * av[ni].x + c3 * av[ni].y;
            d0 += c0 * dv[ni].x + c1 * dv[ni].y;
            d1 += c2 * dv[ni].x + c3 * dv[ni].y;
        }
        // reduce over the 4 lanes of each group (t4 bits = lane bits 0,1)
#pragma unroll
        for (int o = 1; o <= 2; o <<= 1) {
            s0 += __shfl_xor_sync(0xffffffffu, s0, o);
            s1 += __shfl_xor_sync(0xffffffffu, s1, o);
            d0 += __shfl_xor_sync(0xffffffffu, d0, o);
            d1 += __shfl_xor_sync(0xffffffffu, d1, o);
        }
        if (t4 == 0) {
            if (r0 < M) { s_out[r0 * H + head] = s0; d_out[r0 * H + head] = d0; }
            if (r1 < M) { s_out[r1 * H + head] = s1; d_out[r1 * H + head] = d1; }
        }
    }
}

// ---------------------------------------------------------------------------
// Fused GAT per-node kernel: one warp per destination node.
// ---------------------------------------------------------------------------
template <int H>
__global__ __launch_bounds__(256) void gat_fused_kernel(
    const int* __restrict__ ptr, const int* __restrict__ csr,
    const float* __restrict__ s, const float* __restrict__ dco,
    const float* __restrict__ xp, const float* __restrict__ bias,
    float* __restrict__ out, int N)
{
    constexpr int F = H * 64;
    constexpr int PL = F / 32;  // floats per lane (8 for H=4, 2 for H=1)

    int warp = (blockIdx.x * blockDim.x + threadIdx.x) >> 5;
    int lane = threadIdx.x & 31;
    if (warp >= N) return;
    int n = warp;
    int beg = __ldg(&ptr[n]);
    int end = __ldg(&ptr[n + 1]);

    float dh[H];
#pragma unroll
    for (int h = 0; h < H; h++) dh[h] = __ldg(&dco[n * H + h]);

    // Pass 1: online max + sum per head
    float m[H], ssum[H];
#pragma unroll
    for (int h = 0; h < H; h++) { m[h] = -1e30f; ssum[h] = 0.f; }

    for (int i = beg + lane; i < end; i += 32) {
        int src = __ldg(&csr[i]);
        float sv[H];
        if (H == 4) {
            float4 t4 = __ldg((const float4*)s + src);
            sv[0] = t4.x; sv[1] = t4.y; sv[2] = t4.z; sv[3] = t4.w;
        } else {
            sv[0] = __ldg(&s[src]);
        }
#pragma unroll
        for (int h = 0; h < H; h++) {
            float e = sv[h] + dh[h];
            e = e > 0.f ? e : NEG_SLOPE * e;
            float nm = fmaxf(m[h], e);
            ssum[h] = ssum[h] * __expf(m[h] - nm) + __expf(e - nm);
            m[h] = nm;
        }
    }
#pragma unroll
    for (int o = 16; o > 0; o >>= 1) {
#pragma unroll
        for (int h = 0; h < H; h++) {
            float om = __shfl_xor_sync(0xffffffffu, m[h], o);
            float os = __shfl_xor_sync(0xffffffffu, ssum[h], o);
            float nm = fmaxf(m[h], om);
            ssum[h] = ssum[h] * __expf(m[h] - nm) + os * __expf(om - nm);
            m[h] = nm;
        }
    }

    // Pass 2: aggregate
    const int myh = (lane * PL) >> 6;
    const float mh = m[myh];
    const float iv = 1.f / (ssum[myh] + 1e-16f);
    const float dmy = dh[myh];

    float acc[PL];
#pragma unroll
    for (int j = 0; j < PL; j++) acc[j] = 0.f;

#pragma unroll 2
    for (int i = beg; i < end; i++) {
        int src = __ldg(&csr[i]);  // uniform within warp -> broadcast
        float e = __ldg(&s[src * H + myh]) + dmy;
        e = e > 0.f ? e : NEG_SLOPE * e;
        float alpha = __expf(e - mh) * iv;
        if (PL == 8) {
            const float4* xr = (const float4*)(xp + (size_t)src * F);
            float4 v0 = __ldg(xr + lane * 2);
            float4 v1 = __ldg(xr + lane * 2 + 1);
            acc[0] += alpha * v0.x; acc[1] += alpha * v0.y;
            acc[2] += alpha * v0.z; acc[3] += alpha * v0.w;
            acc[4] += alpha * v1.x; acc[5] += alpha * v1.y;
            acc[6] += alpha * v1.z; acc[7] += alpha * v1.w;
        } else {
            float2 v = __ldg((const float2*)(xp + (size_t)src * F) + lane);
            acc[0] += alpha * v.x;
            acc[1] += alpha * v.y;
        }
    }

#pragma unroll
    for (int j = 0; j < PL; j++) {
        float v = acc[j] + __ldg(&bias[lane * PL + j]);
        acc[j] = v > 0.f ? v : 0.f;
    }
    if (PL == 8) {
        float4* orow = (float4*)(out + (size_t)n * F);
        orow[lane * 2]     = make_float4(acc[0], acc[1], acc[2], acc[3]);
        orow[lane * 2 + 1] = make_float4(acc[4], acc[5], acc[6], acc[7]);
    } else {
        ((float2*)(out + (size_t)n * F))[lane] = make_float2(acc[0], acc[1]);
    }
}

// ---------------------------------------------------------------------------
// Final FC: out[n,10] = h[n,64] @ Wfc + bfc
// ---------------------------------------------------------------------------
__global__ void fc_kernel(const float* __restrict__ h, const float* __restrict__ W,
                          const float* __restrict__ b, float* __restrict__ out, int N)
{
    int tid = blockIdx.x * blockDim.x + threadIdx.x;
    if (tid >= N * 10) return;
    int n = tid / 10, j = tid - n * 10;
    const float* row = h + (size_t)n * 64;
    float acc = __ldg(&b[j]);
#pragma unroll
    for (int k = 0; k < 64; k++)
        acc += row[k] * __ldg(&W[k * 10 + j]);
    out[tid] = acc;
}

// ---------------------------------------------------------------------------
// Orchestration
// ---------------------------------------------------------------------------
template <int H>
static void run_gat_layer(const float* act_in, int K, int N,
                          const float* W, const float* a_src, const float* a_dst,
                          const float* b, const int* ptr, const int* csr,
                          float* xp, float* s, float* d, float* out)
{
    const int F = H * 64;
    if (F == 256)
        mma_gemm_kernel<128><<<dim3(F / 128, ceil_div(N, 128)), 256>>>(
            act_in, W, xp, N, F, K, a_src, a_dst, s, d, H);
    else
        mma_gemm_kernel<64><<<dim3(F / 64, ceil_div(N, 128)), 256>>>(
            act_in, W, xp, N, F, K, a_src, a_dst, s, d, H);
    gat_fused_kernel<H><<<ceil_div(N * 32, 256), 256>>>(ptr, csr, s, d, xp, b, out, N);
}

extern "C" void kernel_launch(void* const* d_in, const int* in_sizes, int n_in,
                              void* d_out, int out_size)
{
    const float* x    = (const float*)d_in[0];
    const int*   ei   = (const int*)d_in[1];
    const float* W1   = (const float*)d_in[2];
    const float* as1  = (const float*)d_in[3];
    const float* ad1  = (const float*)d_in[4];
    const float* b1   = (const float*)d_in[5];
    const float* W2   = (const float*)d_in[6];
    const float* as2  = (const float*)d_in[7];
    const float* ad2  = (const float*)d_in[8];
    const float* b2   = (const float*)d_in[9];
    const float* W3   = (const float*)d_in[10];
    const float* as3  = (const float*)d_in[11];
    const float* ad3  = (const float*)d_in[12];
    const float* b3   = (const float*)d_in[13];
    const float* Wfc  = (const float*)d_in[14];
    const float* bfc  = (const float*)d_in[15];
    float* out = (float*)d_out;

    int N = in_sizes[0] / 128;
    int E = in_sizes[1] / 2;
    int Etot = E + N;

    float *bufA, *bufB, *s, *d;
    int *count, *excl, *cursor, *ptr, *bsum, *csr;
    cudaGetSymbolAddress((void**)&bufA, g_bufA);
    cudaGetSymbolAddress((void**)&bufB, g_bufB);
    cudaGetSymbolAddress((void**)&s, g_s);
    cudaGetSymbolAddress((void**)&d, g_d);
    cudaGetSymbolAddress((void**)&count, g_count);
    cudaGetSymbolAddress((void**)&excl, g_excl);
    cudaGetSymbolAddress((void**)&cursor, g_cursor);
    cudaGetSymbolAddress((void**)&ptr, g_ptr);
    cudaGetSymbolAddress((void**)&bsum, g_bsum);
    cudaGetSymbolAddress((void**)&csr, g_csr);

    // --- CSR build (by destination) ---
    int nb = ceil_div(N, SCAN_BS);
    zero_count_kernel<<<ceil_div(N, 256), 256>>>(count, N);
    count_kernel<<<ceil_div(Etot, 256), 256>>>(ei, E, Etot, count);
    scan_block_kernel<<<nb, SCAN_BS>>>(count, excl, bsum, N);
    scan_sums_kernel<<<1, 256>>>(bsum, nb);
    scan_finish_kernel<<<ceil_div(N, 256), 256>>>(excl, bsum, ptr, cursor, N, Etot);
    scatter_kernel<<<ceil_div(Etot, 256), 256>>>(ei, E, Etot, cursor, csr);

    // --- Layers ---
    run_gat_layer<4>(x,    128, N, W1, as1, ad1, b1, ptr, csr, bufA, s, d, bufB);
    run_gat_layer<4>(bufB, 256, N, W2, as2, ad2, b2, ptr, csr, bufA, s, d, bufB);
    run_gat_layer<1>(bufB, 256, N, W3, as3, ad3, b3, ptr, csr, bufA, s, d, bufB);

    // --- FC ---
    fc_kernel<<<ceil_div(N * 10, 256), 256>>>(bufB, Wfc, bfc, out, N);
}

// round 5
// speedup vs baseline: 2.6965x; 1.0786x over previous
#include <cuda_runtime.h>
#include <cuda_bf16.h>
#include <math.h>
#include <stdint.h>

// ---------------------------------------------------------------------------
// GAT: 3 layers (H=4,C=64) -> (H=4,C=64) -> (H=1,C=64) -> FC 64->10
// N=50000 nodes, E=800000 edges (+N self loops)
// R4: bf16 message path — GEMM stores xp as bf16 (s/d still from fp32 accs),
// gather reads bf16 (halves L2 traffic), accumulation stays fp32.
// ---------------------------------------------------------------------------

#define MAX_N 50000
#define MAX_E 800000
#define MAX_ETOT (MAX_E + MAX_N)
#define NEG_SLOPE 0.2f
#define SCAN_BS 512

// Scratch (static __device__ globals; allocation-free)
__device__ float          g_bufB[MAX_N * 256];   // fp32 activations (layer I/O)
__device__ __nv_bfloat16  g_xpb[MAX_N * 256];    // bf16 transformed features
__device__ float g_s[MAX_N * 4];
__device__ float g_d[MAX_N * 4];
__device__ int   g_count[MAX_N];
__device__ int   g_excl[MAX_N];
__device__ int   g_cursor[MAX_N];
__device__ int   g_ptr[MAX_N + 1];
__device__ int   g_bsum[256];
__device__ int   g_csr[MAX_ETOT];

static inline int ceil_div(int a, int b) { return (a + b - 1) / b; }

// ---------------------------------------------------------------------------
// CSR build
// ---------------------------------------------------------------------------
__global__ void zero_count_kernel(int* __restrict__ count, int N)
{
    int i = blockIdx.x * blockDim.x + threadIdx.x;
    if (i < N) count[i] = 0;
}

__global__ void count_kernel(const int* __restrict__ ei, int E, int Etot,
                             int* __restrict__ count)
{
    int e = blockIdx.x * blockDim.x + threadIdx.x;
    if (e >= Etot) return;
    int dst = (e < E) ? __ldg(&ei[E + e]) : (e - E);
    atomicAdd(&count[dst], 1);
}

__global__ void scan_block_kernel(const int* __restrict__ count, int* __restrict__ excl,
                                  int* __restrict__ bsum, int N)
{
    __shared__ int sh[SCAN_BS];
    int t = threadIdx.x;
    int idx = blockIdx.x * SCAN_BS + t;
    int v = (idx < N) ? count[idx] : 0;
    sh[t] = v;
    __syncthreads();
#pragma unroll
    for (int o = 1; o < SCAN_BS; o <<= 1) {
        int add = (t >= o) ? sh[t - o] : 0;
        __syncthreads();
        sh[t] += add;
        __syncthreads();
    }
    if (idx < N) excl[idx] = sh[t] - v;
    if (t == SCAN_BS - 1) bsum[blockIdx.x] = sh[t];
}

__global__ void scan_sums_kernel(int* __restrict__ bsum, int nb)
{
    __shared__ int sh[256];
    int t = threadIdx.x;
    int v = (t < nb) ? bsum[t] : 0;
    sh[t] = v;
    __syncthreads();
#pragma unroll
    for (int o = 1; o < 256; o <<= 1) {
        int add = (t >= o) ? sh[t - o] : 0;
        __syncthreads();
        sh[t] += add;
        __syncthreads();
    }
    if (t < nb) bsum[t] = sh[t] - v;  // exclusive
}

__global__ void scan_finish_kernel(const int* __restrict__ excl, const int* __restrict__ bsum,
                                   int* __restrict__ ptr, int* __restrict__ cursor,
                                   int N, int Etot)
{
    int i = blockIdx.x * blockDim.x + threadIdx.x;
    if (i < N) {
        int p = excl[i] + bsum[i / SCAN_BS];
        ptr[i] = p;
        cursor[i] = p;
    }
    if (i == 0) ptr[N] = Etot;
}

__global__ void scatter_kernel(const int* __restrict__ ei, int E, int Etot,
                               int* __restrict__ cursor, int* __restrict__ csr)
{
    int e = blockIdx.x * blockDim.x + threadIdx.x;
    if (e >= Etot) return;
    int src, dst;
    if (e < E) { src = __ldg(&ei[e]); dst = __ldg(&ei[E + e]); }
    else       { src = dst = e - E; }
    int pos = atomicAdd(&cursor[dst], 1);
    csr[pos] = src;
}

// ---------------------------------------------------------------------------
// TF32 helpers
// ---------------------------------------------------------------------------
__device__ __forceinline__ uint32_t f2tf32(float f)
{
    uint32_t o;
    asm("cvt.rna.tf32.f32 %0, %1;" : "=r"(o) : "f"(f));
    return o;
}

__device__ __forceinline__ void mma_tf32(float* c, const uint32_t* a, const uint32_t* b)
{
    asm volatile(
        "mma.sync.aligned.m16n8k8.row.col.f32.tf32.tf32.f32 "
        "{%0,%1,%2,%3}, {%4,%5,%6,%7}, {%8,%9}, {%0,%1,%2,%3};\n"
        : "+f"(c[0]), "+f"(c[1]), "+f"(c[2]), "+f"(c[3])
        : "r"(a[0]), "r"(a[1]), "r"(a[2]), "r"(a[3]), "r"(b[0]), "r"(b[1]));
}

// ---------------------------------------------------------------------------
// TF32 tensor-core GEMM: Cb[M,N](bf16) = A[M,K] @ B[K,N], fp32 inputs.
// BM=128, BK=32, 256 threads (8 warps), warp tile 32x64 (BN=128) / 16x64 (BN=64).
// Fused epilogue: s/d attention dots from the fp32 accumulators; C stored bf16.
// Requires K % 32 == 0, N % BN_ == 0.
// ---------------------------------------------------------------------------
template <int BN_>
__global__ __launch_bounds__(256) void mma_gemm_kernel(
    const float* __restrict__ A, const float* __restrict__ B,
    __nv_bfloat16* __restrict__ Cb, int M, int N, int K,
    const float* __restrict__ a_src, const float* __restrict__ a_dst,
    float* __restrict__ s_out, float* __restrict__ d_out, int H)
{
    constexpr int BM_ = 128, BK_ = 32;
    constexpr int MI = (BN_ == 128) ? 2 : 1;   // 16-row mma tiles per warp
    constexpr int NI = 8;                      // 8-col mma tiles per warp
    constexpr int AV = 4;                      // float4 A loads/thread
    constexpr int BV = (BK_ * BN_) / 1024;     // float4 B loads/thread (4 or 2)

    __shared__ uint32_t As[BM_][40];           // [m][k], pad -> conflict-free frag reads
    __shared__ uint32_t Bs[BK_][BN_ + 8];      // [k][n], pad -> conflict-free frag reads

    const int tid = threadIdx.x;
    const int wid = tid >> 5;
    const int lane = tid & 31;
    const int g = lane >> 2;      // groupID
    const int t4 = lane & 3;      // threadID_in_group

    const int rowBase = blockIdx.y * BM_;
    const int colBase = blockIdx.x * BN_;
    const int warp_m = (BN_ == 128) ? (wid >> 1) * 32 : wid * 16;
    const int warp_n = (BN_ == 128) ? (wid & 1) * 64 : 0;

    float4 aReg[AV];
    float4 bReg[BV];

    auto loadRegs = [&](int k0) {
#pragma unroll
        for (int l = 0; l < AV; l++) {
            int li = tid + l * 256;
            int m = li >> 3;
            int k4 = (li & 7) * 4;
            int row = rowBase + m;
            aReg[l] = (row < M) ? *(const float4*)&A[(size_t)row * K + k0 + k4]
                                : make_float4(0.f, 0.f, 0.f, 0.f);
        }
#pragma unroll
        for (int l = 0; l < BV; l++) {
            int li = tid + l * 256;
            int r = li / (BN_ / 4);
            int c4 = (li % (BN_ / 4)) * 4;
            bReg[l] = *(const float4*)&B[(size_t)(k0 + r) * N + colBase + c4];
        }
    };
    auto storeSmem = [&]() {
#pragma unroll
        for (int l = 0; l < AV; l++) {
            int li = tid + l * 256;
            int m = li >> 3;
            int k4 = (li & 7) * 4;
            As[m][k4 + 0] = f2tf32(aReg[l].x);
            As[m][k4 + 1] = f2tf32(aReg[l].y);
            As[m][k4 + 2] = f2tf32(aReg[l].z);
            As[m][k4 + 3] = f2tf32(aReg[l].w);
        }
#pragma unroll
        for (int l = 0; l < BV; l++) {
            int li = tid + l * 256;
            int r = li / (BN_ / 4);
            int c4 = (li % (BN_ / 4)) * 4;
            Bs[r][c4 + 0] = f2tf32(bReg[l].x);
            Bs[r][c4 + 1] = f2tf32(bReg[l].y);
            Bs[r][c4 + 2] = f2tf32(bReg[l].z);
            Bs[r][c4 + 3] = f2tf32(bReg[l].w);
        }
    };

    float acc[MI][NI][4];
#pragma unroll
    for (int mi = 0; mi < MI; mi++)
#pragma unroll
        for (int ni = 0; ni < NI; ni++)
#pragma unroll
            for (int j = 0; j < 4; j++) acc[mi][ni][j] = 0.f;

    const int tiles = K / BK_;
    loadRegs(0);

    for (int t = 0; t < tiles; t++) {
        storeSmem();
        __syncthreads();
        if (t + 1 < tiles) loadRegs((t + 1) * BK_);

#pragma unroll
        for (int kk = 0; kk < BK_ / 8; kk++) {
            uint32_t af[MI][4], bf[NI][2];
#pragma unroll
            for (int mi = 0; mi < MI; mi++) {
                int m = warp_m + mi * 16;
                af[mi][0] = As[m + g][kk * 8 + t4];
                af[mi][1] = As[m + 8 + g][kk * 8 + t4];
                af[mi][2] = As[m + g][kk * 8 + t4 + 4];
                af[mi][3] = As[m + 8 + g][kk * 8 + t4 + 4];
            }
#pragma unroll
            for (int ni = 0; ni < NI; ni++) {
                int n = warp_n + ni * 8 + g;
                bf[ni][0] = Bs[kk * 8 + t4][n];
                bf[ni][1] = Bs[kk * 8 + t4 + 4][n];
            }
#pragma unroll
            for (int mi = 0; mi < MI; mi++)
#pragma unroll
                for (int ni = 0; ni < NI; ni++)
                    mma_tf32(acc[mi][ni], af[mi], bf[ni]);
        }
        __syncthreads();
    }

    // ---- Epilogue: bf16 C store + fused attention coefficients (fp32 accs) ----
    const int head = (colBase + warp_n) >> 6;
    const float* ah = a_src + head * 64;
    const float* dh = a_dst + head * 64;
    float2 av[NI], dv[NI];
#pragma unroll
    for (int ni = 0; ni < NI; ni++) {
        av[ni] = *(const float2*)&ah[ni * 8 + 2 * t4];
        dv[ni] = *(const float2*)&dh[ni * 8 + 2 * t4];
    }

#pragma unroll
    for (int mi = 0; mi < MI; mi++) {
        int r0 = rowBase + warp_m + mi * 16 + g;
        int r1 = r0 + 8;
        float s0 = 0.f, s1 = 0.f, d0 = 0.f, d1 = 0.f;
#pragma unroll
        for (int ni = 0; ni < NI; ni++) {
            float c0 = acc[mi][ni][0], c1 = acc[mi][ni][1];
            float c2 = acc[mi][ni][2], c3 = acc[mi][ni][3];
            int col = colBase + warp_n + ni * 8 + 2 * t4;
            if (r0 < M) *(__nv_bfloat162*)&Cb[(size_t)r0 * N + col] = __floats2bfloat162_rn(c0, c1);
            if (r1 < M) *(__nv_bfloat162*)&Cb[(size_t)r1 * N + col] = __floats2bfloat162_rn(c2, c3);
            s0 += c0 * av[ni].x + c1 * av[ni].y;
            s1 += c2 * av[ni].x + c3 * av[ni].y;
            d0 += c0 * dv[ni].x + c1 * dv[ni].y;
            d1 += c2 * dv[ni].x + c3 * dv[ni].y;
        }
#pragma unroll
        for (int o = 1; o <= 2; o <<= 1) {
            s0 += __shfl_xor_sync(0xffffffffu, s0, o);
            s1 += __shfl_xor_sync(0xffffffffu, s1, o);
            d0 += __shfl_xor_sync(0xffffffffu, d0, o);
            d1 += __shfl_xor_sync(0xffffffffu, d1, o);
        }
        if (t4 == 0) {
            if (r0 < M) { s_out[r0 * H + head] = s0; d_out[r0 * H + head] = d0; }
            if (r1 < M) { s_out[r1 * H + head] = s1; d_out[r1 * H + head] = d1; }
        }
    }
}

// ---------------------------------------------------------------------------
// Fused GAT per-node kernel: one warp per destination node, bf16 gather.
// ---------------------------------------------------------------------------
template <int H>
__global__ __launch_bounds__(256) void gat_fused_kernel(
    const int* __restrict__ ptr, const int* __restrict__ csr,
    const float* __restrict__ s, const float* __restrict__ dco,
    const __nv_bfloat16* __restrict__ xpb, const float* __restrict__ bias,
    float* __restrict__ out, int N)
{
    constexpr int F = H * 64;
    constexpr int PL = F / 32;  // floats per lane (8 for H=4, 2 for H=1)

    int warp = (blockIdx.x * blockDim.x + threadIdx.x) >> 5;
    int lane = threadIdx.x & 31;
    if (warp >= N) return;
    int n = warp;
    int beg = __ldg(&ptr[n]);
    int end = __ldg(&ptr[n + 1]);

    float dh[H];
#pragma unroll
    for (int h = 0; h < H; h++) dh[h] = __ldg(&dco[n * H + h]);

    // Pass 1: online max + sum per head
    float m[H], ssum[H];
#pragma unroll
    for (int h = 0; h < H; h++) { m[h] = -1e30f; ssum[h] = 0.f; }

    for (int i = beg + lane; i < end; i += 32) {
        int src = __ldg(&csr[i]);
        float sv[H];
        if (H == 4) {
            float4 t4 = __ldg((const float4*)s + src);
            sv[0] = t4.x; sv[1] = t4.y; sv[2] = t4.z; sv[3] = t4.w;
        } else {
            sv[0] = __ldg(&s[src]);
        }
#pragma unroll
        for (int h = 0; h < H; h++) {
            float e = sv[h] + dh[h];
            e = e > 0.f ? e : NEG_SLOPE * e;
            float nm = fmaxf(m[h], e);
            ssum[h] = ssum[h] * __expf(m[h] - nm) + __expf(e - nm);
            m[h] = nm;
        }
    }
#pragma unroll
    for (int o = 16; o > 0; o >>= 1) {
#pragma unroll
        for (int h = 0; h < H; h++) {
            float om = __shfl_xor_sync(0xffffffffu, m[h], o);
            float os = __shfl_xor_sync(0xffffffffu, ssum[h], o);
            float nm = fmaxf(m[h], om);
            ssum[h] = ssum[h] * __expf(m[h] - nm) + os * __expf(om - nm);
            m[h] = nm;
        }
    }

    // Pass 2: aggregate (bf16 messages, fp32 accumulate)
    const int myh = (lane * PL) >> 6;
    const float mh = m[myh];
    const float iv = 1.f / (ssum[myh] + 1e-16f);
    const float dmy = dh[myh];

    float acc[PL];
#pragma unroll
    for (int j = 0; j < PL; j++) acc[j] = 0.f;

#pragma unroll 4
    for (int i = beg; i < end; i++) {
        int src = __ldg(&csr[i]);  // uniform within warp -> broadcast
        float e = __ldg(&s[src * H + myh]) + dmy;
        e = e > 0.f ? e : NEG_SLOPE * e;
        float alpha = __expf(e - mh) * iv;
        if (PL == 8) {
            // one LDG.128 per lane: 8 bf16 = full lane slice
            uint4 v = __ldg((const uint4*)(xpb + (size_t)src * F) + lane);
            float2 f0 = __bfloat1622float2(*(__nv_bfloat162*)&v.x);
            float2 f1 = __bfloat1622float2(*(__nv_bfloat162*)&v.y);
            float2 f2 = __bfloat1622float2(*(__nv_bfloat162*)&v.z);
            float2 f3 = __bfloat1622float2(*(__nv_bfloat162*)&v.w);
            acc[0] += alpha * f0.x; acc[1] += alpha * f0.y;
            acc[2] += alpha * f1.x; acc[3] += alpha * f1.y;
            acc[4] += alpha * f2.x; acc[5] += alpha * f2.y;
            acc[6] += alpha * f3.x; acc[7] += alpha * f3.y;
        } else {
            uint32_t v = __ldg((const uint32_t*)(xpb + (size_t)src * F) + lane);
            float2 f = __bfloat1622float2(*(__nv_bfloat162*)&v);
            acc[0] += alpha * f.x;
            acc[1] += alpha * f.y;
        }
    }

#pragma unroll
    for (int j = 0; j < PL; j++) {
        float v = acc[j] + __ldg(&bias[lane * PL + j]);
        acc[j] = v > 0.f ? v : 0.f;
    }
    if (PL == 8) {
        float4* orow = (float4*)(out + (size_t)n * F);
        orow[lane * 2]     = make_float4(acc[0], acc[1], acc[2], acc[3]);
        orow[lane * 2 + 1] = make_float4(acc[4], acc[5], acc[6], acc[7]);
    } else {
        ((float2*)(out + (size_t)n * F))[lane] = make_float2(acc[0], acc[1]);
    }
}

// ---------------------------------------------------------------------------
// Final FC: out[n,10] = h[n,64] @ Wfc + bfc
// ---------------------------------------------------------------------------
__global__ void fc_kernel(const float* __restrict__ h, const float* __restrict__ W,
                          const float* __restrict__ b, float* __restrict__ out, int N)
{
    int tid = blockIdx.x * blockDim.x + threadIdx.x;
    if (tid >= N * 10) return;
    int n = tid / 10, j = tid - n * 10;
    const float* row = h + (size_t)n * 64;
    float acc = __ldg(&b[j]);
#pragma unroll
    for (int k = 0; k < 64; k++)
        acc += row[k] * __ldg(&W[k * 10 + j]);
    out[tid] = acc;
}

// ---------------------------------------------------------------------------
// Orchestration
// ---------------------------------------------------------------------------
template <int H>
static void run_gat_layer(const float* act_in, int K, int N,
                          const float* W, const float* a_src, const float* a_dst,
                          const float* b, const int* ptr, const int* csr,
                          __nv_bfloat16* xpb, float* s, float* d, float* out)
{
    const int F = H * 64;
    if (F == 256)
        mma_gemm_kernel<128><<<dim3(F / 128, ceil_div(N, 128)), 256>>>(
            act_in, W, xpb, N, F, K, a_src, a_dst, s, d, H);
    else
        mma_gemm_kernel<64><<<dim3(F / 64, ceil_div(N, 128)), 256>>>(
            act_in, W, xpb, N, F, K, a_src, a_dst, s, d, H);
    gat_fused_kernel<H><<<ceil_div(N * 32, 256), 256>>>(ptr, csr, s, d, xpb, b, out, N);
}

extern "C" void kernel_launch(void* const* d_in, const int* in_sizes, int n_in,
                              void* d_out, int out_size)
{
    const float* x    = (const float*)d_in[0];
    const int*   ei   = (const int*)d_in[1];
    const float* W1   = (const float*)d_in[2];
    const float* as1  = (const float*)d_in[3];
    const float* ad1  = (const float*)d_in[4];
    const float* b1   = (const float*)d_in[5];
    const float* W2   = (const float*)d_in[6];
    const float* as2  = (const float*)d_in[7];
    const float* ad2  = (const float*)d_in[8];
    const float* b2   = (const float*)d_in[9];
    const float* W3   = (const float*)d_in[10];
    const float* as3  = (const float*)d_in[11];
    const float* ad3  = (const float*)d_in[12];
    const float* b3   = (const float*)d_in[13];
    const float* Wfc  = (const float*)d_in[14];
    const float* bfc  = (const float*)d_in[15];
    float* out = (float*)d_out;

    int N = in_sizes[0] / 128;
    int E = in_sizes[1] / 2;
    int Etot = E + N;

    float *bufB, *s, *d;
    __nv_bfloat16* xpb;
    int *count, *excl, *cursor, *ptr, *bsum, *csr;
    cudaGetSymbolAddress((void**)&bufB, g_bufB);
    cudaGetSymbolAddress((void**)&xpb, g_xpb);
    cudaGetSymbolAddress((void**)&s, g_s);
    cudaGetSymbolAddress((void**)&d, g_d);
    cudaGetSymbolAddress((void**)&count, g_count);
    cudaGetSymbolAddress((void**)&excl, g_excl);
    cudaGetSymbolAddress((void**)&cursor, g_cursor);
    cudaGetSymbolAddress((void**)&ptr, g_ptr);
    cudaGetSymbolAddress((void**)&bsum, g_bsum);
    cudaGetSymbolAddress((void**)&csr, g_csr);

    // --- CSR build (by destination) ---
    int nb = ceil_div(N, SCAN_BS);
    zero_count_kernel<<<ceil_div(N, 256), 256>>>(count, N);
    count_kernel<<<ceil_div(Etot, 256), 256>>>(ei, E, Etot, count);
    scan_block_kernel<<<nb, SCAN_BS>>>(count, excl, bsum, N);
    scan_sums_kernel<<<1, 256>>>(bsum, nb);
    scan_finish_kernel<<<ceil_div(N, 256), 256>>>(excl, bsum, ptr, cursor, N, Etot);
    scatter_kernel<<<ceil_div(Etot, 256), 256>>>(ei, E, Etot, cursor, csr);

    // --- Layers ---
    run_gat_layer<4>(x,    128, N, W1, as1, ad1, b1, ptr, csr, xpb, s, d, bufB);
    run_gat_layer<4>(bufB, 256, N, W2, as2, ad2, b2, ptr, csr, xpb, s, d, bufB);
    run_gat_layer<1>(bufB, 256, N, W3, as3, ad3, b3, ptr, csr, xpb, s, d, bufB);

    // --- FC ---
    fc_kernel<<<ceil_div(N * 10, 256), 256>>>(bufB, Wfc, bfc, out, N);
}